// round 4
// baseline (speedup 1.0000x reference)
#include <cuda_runtime.h>
#include <cstdint>

// ---------------------------------------------------------------------------
// FocalLoss_84645215469642 — sm_100a
// Inputs (metadata order):
//   d_in[0] classifications [B, A, C]  float32
//   d_in[1] regressions     [B, A, 3]  float32
//   d_in[2] anchors         [1, A, 3]  float32
//   d_in[3] annotations     [B, M, 4]  float32   (x, y, alpha, class; class==-1 invalid)
// Output: 3 float32 scalars: cls_loss, xy_loss, ang_loss (batch means)
// ---------------------------------------------------------------------------

#define MAX_B 8
#define MAX_A (1 << 18)
#define MAX_M 64
#define MAX_SEG (MAX_A / 256)
#define NSLOT 32

// scratch (device globals — no allocations allowed)
__device__ uint16_t g_meta[MAX_B * MAX_A];        // amin(6b) | state(2b) | class(8b)
__device__ int      g_segcnt[MAX_B * MAX_SEG];    // positives per 256-anchor segment
__device__ int      g_table[MAX_B * MAX_M];       // table[k] = ann idx of k-th positive anchor
__device__ int      g_numpos[MAX_B];
__device__ double   g_cls_part[MAX_B * NSLOT];
__device__ double   g_xy_part [MAX_B * NSLOT];
__device__ double   g_ang_part[MAX_B * NSLOT];

// ---------------------------------------------------------------------------
// assign: one thread per anchor. argmin over annotations, 3-state target,
// packed meta; block-level positive count -> g_segcnt.
// ---------------------------------------------------------------------------
__global__ void assign_kernel(const float* __restrict__ anchors,
                              const float* __restrict__ ann,
                              int A, int M) {
    __shared__ float s_ann[MAX_M * 4];
    __shared__ int   s_wcnt[8];
    int b = blockIdx.y;
    for (int i = threadIdx.x; i < M * 4; i += blockDim.x)
        s_ann[i] = ann[b * M * 4 + i];
    __syncthreads();

    int a = blockIdx.x * blockDim.x + threadIdx.x;
    bool in = (a < A);
    int aa = in ? a : 0;

    float ax  = anchors[aa * 3 + 0];
    float ay  = anchors[aa * 3 + 1];
    float aal = anchors[aa * 3 + 2];

    float best = 3.4e38f;
    int bi = 0;
    #pragma unroll 4
    for (int m = 0; m < M; m++) {
        float cx = s_ann[m * 4 + 0];
        float cy = s_ann[m * 4 + 1];
        bool valid = (s_ann[m * 4 + 3] != -1.0f);
        float dx = ax - cx, dy = ay - cy;
        float d2 = valid ? fmaf(dx, dx, dy * dy) : 1e18f;   // BIG^2
        if (d2 < best) { best = d2; bi = m; }
    }
    float dal = fabsf(aal - s_ann[bi * 4 + 2]);

    // pos: dxy<=5 && dal<=0.3 ; neg: dxy>=7.5 || dal>=0.45 ; else ignore
    bool pos = (best <= 25.0f) && (dal <= 0.3f);
    int state;
    if (pos)                                 state = 2;
    else if (best >= 56.25f || dal >= 0.45f) state = 1;
    else                                     state = 0;

    int cls = (int)s_ann[bi * 4 + 3];
    if (cls < 0) cls = 0;

    if (in)
        g_meta[b * A + a] = (uint16_t)((bi & 63) | (state << 6) | ((cls & 0xFF) << 8));

    // segment positive count
    unsigned bal = __ballot_sync(0xffffffffu, pos && in);
    int lane = threadIdx.x & 31, wid = threadIdx.x >> 5;
    if (lane == 0) s_wcnt[wid] = __popc(bal);
    __syncthreads();
    if (threadIdx.x == 0) {
        int tot = 0;
        #pragma unroll
        for (int w = 0; w < 8; w++) tot += s_wcnt[w];
        g_segcnt[b * MAX_SEG + blockIdx.x] = tot;
    }
}

// ---------------------------------------------------------------------------
// scan: one block per image. Prefix-scan segment counts -> num_pos; walk only
// segments whose exclusive prefix < M to fill table. Also zeroes accumulators.
// ---------------------------------------------------------------------------
__global__ void scan_kernel(int A, int M, int NSEG) {
    int b = blockIdx.x;
    int t = threadIdx.x;
    __shared__ int s_dat[256];

    if (t < NSLOT) {
        g_cls_part[b * NSLOT + t] = 0.0;
        g_xy_part [b * NSLOT + t] = 0.0;
        g_ang_part[b * NSLOT + t] = 0.0;
    }
    for (int i = t; i < M; i += blockDim.x) g_table[b * M + i] = 0;
    __syncthreads();

    int base = 0;
    for (int s0 = 0; s0 < NSEG; s0 += blockDim.x) {
        int seg = s0 + t;
        int cnt = (seg < NSEG) ? g_segcnt[b * MAX_SEG + seg] : 0;
        s_dat[t] = cnt;
        __syncthreads();
        // Hillis-Steele inclusive scan over 256
        #pragma unroll
        for (int off = 1; off < 256; off <<= 1) {
            int v = (t >= off) ? s_dat[t - off] : 0;
            __syncthreads();
            s_dat[t] += v;
            __syncthreads();
        }
        int incl  = s_dat[t];
        int total = s_dat[255];
        int epref = base + incl - cnt;

        if (seg < NSEG && cnt > 0 && epref < M) {
            int r = epref;
            int abase = b * A + seg * 256;
            int lim = min(256, A - seg * 256);
            #pragma unroll 8
            for (int j = 0; j < lim; j++) {
                if (r >= M) break;
                uint32_t mm = g_meta[abase + j];
                if (((mm >> 6) & 3u) == 2u) { g_table[b * M + r] = (int)(mm & 63u); r++; }
            }
        }
        base += total;
        __syncthreads();
    }
    if (t == 0) g_numpos[b] = base;
}

__device__ __forceinline__ float focal_elem(float c, bool is_one) {
    c = fminf(fmaxf(c, 1e-4f), 0.9999f);
    float o = 1.0f - c;
    float w = is_one ? 0.25f * o * o : 0.75f * c * c;
    float l = -__logf(is_one ? c : o);
    return w * l;
}

__device__ __forceinline__ float smooth_l1(float d) {
    return (d <= 1.0f / 9.0f) ? (4.5f * d * d) : (d - 0.5f / 9.0f);
}

// ---------------------------------------------------------------------------
// fused focal + regression. grid = (NBLK, B), 256 threads.
// thread t: anchor = a0 + (t>>4), channels 4*(t&15)..+3 as float4.
// thread with (t&15)==0 additionally handles the regression loss of its anchor.
// ---------------------------------------------------------------------------
__global__ void fused_kernel(const float* __restrict__ cls,
                             const float* __restrict__ regs,
                             const float* __restrict__ anchors,
                             const float* __restrict__ ann,
                             int A, int C, int M) {
    int b  = blockIdx.y;
    int t  = threadIdx.x;
    int la = t >> 4;       // 0..15
    int c4 = t & 15;       // 0..15

    float cl_acc = 0.0f, xy_acc = 0.0f, ang_acc = 0.0f;

    for (int a0 = blockIdx.x * 16; a0 < A; a0 += gridDim.x * 16) {
        int a = a0 + la;
        if (a >= A) continue;
        uint32_t m = g_meta[b * A + a];
        int state = (int)((m >> 6) & 3u);

        if (state != 0) {
            int tgt = (state == 2) ? (int)(m >> 8) : -1;
            for (int col = c4 * 4; col < C; col += 64) {
                const float4 v = *(const float4*)(cls + (size_t)(b * A + a) * C + col);
                cl_acc += focal_elem(v.x, col + 0 == tgt);
                cl_acc += focal_elem(v.y, col + 1 == tgt);
                cl_acc += focal_elem(v.z, col + 2 == tgt);
                cl_acc += focal_elem(v.w, col + 3 == tgt);
            }
        }

        if (c4 == 0 && state == 2) {
            int gi = g_table[b * M + (m & 63u)];
            const float* g  = ann + (size_t)(b * M + gi) * 4;
            const float* rg = regs + ((size_t)b * A + a) * 3;
            float tx = g[0] - anchors[a * 3 + 0];
            float ty = g[1] - anchors[a * 3 + 1];
            float ta = g[2] - anchors[a * 3 + 2];
            xy_acc  += smooth_l1(fabsf(tx - rg[0])) + smooth_l1(fabsf(ty - rg[1]));
            ang_acc += 1.0f - cosf(ta - rg[2]);
        }
    }

    // block reduce 3 values
    __shared__ float s_c[8], s_x[8], s_a[8];
    #pragma unroll
    for (int o = 16; o > 0; o >>= 1) {
        cl_acc  += __shfl_down_sync(0xffffffffu, cl_acc,  o);
        xy_acc  += __shfl_down_sync(0xffffffffu, xy_acc,  o);
        ang_acc += __shfl_down_sync(0xffffffffu, ang_acc, o);
    }
    int lane = t & 31, wid = t >> 5;
    if (lane == 0) { s_c[wid] = cl_acc; s_x[wid] = xy_acc; s_a[wid] = ang_acc; }
    __syncthreads();
    if (wid == 0) {
        float vc = (lane < 8) ? s_c[lane] : 0.0f;
        float vx = (lane < 8) ? s_x[lane] : 0.0f;
        float va = (lane < 8) ? s_a[lane] : 0.0f;
        #pragma unroll
        for (int o = 4; o > 0; o >>= 1) {
            vc += __shfl_down_sync(0xffffffffu, vc, o);
            vx += __shfl_down_sync(0xffffffffu, vx, o);
            va += __shfl_down_sync(0xffffffffu, va, o);
        }
        if (lane == 0) {
            int slot = blockIdx.x & (NSLOT - 1);
            atomicAdd(&g_cls_part[b * NSLOT + slot], (double)vc);
            if (vx != 0.0f) atomicAdd(&g_xy_part [b * NSLOT + slot], (double)vx);
            if (va != 0.0f) atomicAdd(&g_ang_part[b * NSLOT + slot], (double)va);
        }
    }
}

__global__ void finalize_kernel(float* __restrict__ out, int B) {
    if (threadIdx.x == 0 && blockIdx.x == 0) {
        double cl = 0.0, xy = 0.0, ag = 0.0;
        for (int b = 0; b < B; b++) {
            double sc = 0.0, sx = 0.0, sa = 0.0;
            for (int s = 0; s < NSLOT; s++) {
                sc += g_cls_part[b * NSLOT + s];
                sx += g_xy_part [b * NSLOT + s];
                sa += g_ang_part[b * NSLOT + s];
            }
            double np = (double)max(g_numpos[b], 1);
            cl += sc / np;
            xy += sx / (2.0 * np);
            ag += sa / np;
        }
        out[0] = (float)(cl / B);
        out[1] = (float)(xy / B);
        out[2] = (float)(ag / B);
    }
}

extern "C" void kernel_launch(void* const* d_in, const int* in_sizes, int n_in,
                              void* d_out, int out_size) {
    const float* cls     = (const float*)d_in[0];
    const float* regs    = (const float*)d_in[1];
    const float* anchors = (const float*)d_in[2];
    const float* ann     = (const float*)d_in[3];
    float* out = (float*)d_out;

    int A = in_sizes[2] / 3;                 // anchors [1, A, 3]
    int B = in_sizes[1] / (3 * A);           // regressions [B, A, 3]
    int C = in_sizes[0] / (B * A);           // classifications [B, A, C]
    int M = in_sizes[3] / (4 * B);           // annotations [B, M, 4]
    int NSEG = (A + 255) / 256;

    dim3 ag(NSEG, B);
    assign_kernel<<<ag, 256>>>(anchors, ann, A, M);

    scan_kernel<<<B, 256>>>(A, M, NSEG);

    dim3 fg(512, B);
    fused_kernel<<<fg, 256>>>(cls, regs, anchors, ann, A, C, M);

    finalize_kernel<<<1, 32>>>(out, B);
}

// round 5
// speedup vs baseline: 1.1398x; 1.1398x over previous
#include <cuda_runtime.h>
#include <cstdint>

// ---------------------------------------------------------------------------
// FocalLoss_84645215469642 — sm_100a
// Inputs (metadata order):
//   d_in[0] classifications [B, A, C]  float32
//   d_in[1] regressions     [B, A, 3]  float32
//   d_in[2] anchors         [1, A, 3]  float32
//   d_in[3] annotations     [B, M, 4]  float32   (x, y, alpha, class; class==-1 invalid)
// Output: 3 float32 scalars: cls_loss, xy_loss, ang_loss (batch means)
// ---------------------------------------------------------------------------

#define MAX_B 8
#define MAX_A (1 << 18)
#define MAX_M 64
#define MAX_SEG (MAX_A / 256)
#define NSLOT 32

// scratch (device globals — no allocations allowed)
__device__ uint16_t g_meta[MAX_B * MAX_A];        // amin(6b) | state(2b) | class(8b)
__device__ int      g_segcnt[MAX_B * MAX_SEG];    // positives per 256-anchor segment
__device__ int      g_table[MAX_B * MAX_M];       // table[k] = ann idx of k-th positive anchor
__device__ int      g_numpos[MAX_B];
__device__ double   g_cls_part[MAX_B * NSLOT];
__device__ double   g_xy_part [MAX_B * NSLOT];
__device__ double   g_ang_part[MAX_B * NSLOT];

// ---------------------------------------------------------------------------
// assign: one thread per anchor. argmin over annotations, 3-state target,
// packed meta; block-level positive count -> g_segcnt.
// ---------------------------------------------------------------------------
__global__ void assign_kernel(const float* __restrict__ anchors,
                              const float* __restrict__ ann,
                              int A, int M) {
    __shared__ float s_ann[MAX_M * 4];
    __shared__ int   s_wcnt[8];
    int b = blockIdx.y;
    for (int i = threadIdx.x; i < M * 4; i += blockDim.x)
        s_ann[i] = ann[b * M * 4 + i];
    __syncthreads();

    int a = blockIdx.x * blockDim.x + threadIdx.x;
    bool in = (a < A);
    int aa = in ? a : 0;

    float ax  = anchors[aa * 3 + 0];
    float ay  = anchors[aa * 3 + 1];
    float aal = anchors[aa * 3 + 2];

    float best = 3.4e38f;
    int bi = 0;
    #pragma unroll 4
    for (int m = 0; m < M; m++) {
        float cx = s_ann[m * 4 + 0];
        float cy = s_ann[m * 4 + 1];
        bool valid = (s_ann[m * 4 + 3] != -1.0f);
        float dx = ax - cx, dy = ay - cy;
        float d2 = valid ? fmaf(dx, dx, dy * dy) : 1e18f;   // BIG^2
        if (d2 < best) { best = d2; bi = m; }
    }
    float dal = fabsf(aal - s_ann[bi * 4 + 2]);

    // pos: dxy<=5 && dal<=0.3 ; neg: dxy>=7.5 || dal>=0.45 ; else ignore
    bool pos = (best <= 25.0f) && (dal <= 0.3f);
    int state;
    if (pos)                                 state = 2;
    else if (best >= 56.25f || dal >= 0.45f) state = 1;
    else                                     state = 0;

    int cls = (int)s_ann[bi * 4 + 3];
    if (cls < 0) cls = 0;

    if (in)
        g_meta[b * A + a] = (uint16_t)((bi & 63) | (state << 6) | ((cls & 0xFF) << 8));

    // segment positive count
    unsigned bal = __ballot_sync(0xffffffffu, pos && in);
    int lane = threadIdx.x & 31, wid = threadIdx.x >> 5;
    if (lane == 0) s_wcnt[wid] = __popc(bal);
    __syncthreads();
    if (threadIdx.x == 0) {
        int tot = 0;
        #pragma unroll
        for (int w = 0; w < 8; w++) tot += s_wcnt[w];
        g_segcnt[b * MAX_SEG + blockIdx.x] = tot;
    }
}

// ---------------------------------------------------------------------------
// scan: one block per image. Prefix-scan segment counts -> num_pos; walk only
// segments whose exclusive prefix < M to fill table. Also zeroes accumulators.
// ---------------------------------------------------------------------------
__global__ void scan_kernel(int A, int M, int NSEG) {
    int b = blockIdx.x;
    int t = threadIdx.x;
    __shared__ int s_dat[256];

    if (t < NSLOT) {
        g_cls_part[b * NSLOT + t] = 0.0;
        g_xy_part [b * NSLOT + t] = 0.0;
        g_ang_part[b * NSLOT + t] = 0.0;
    }
    for (int i = t; i < M; i += blockDim.x) g_table[b * M + i] = 0;
    __syncthreads();

    int base = 0;
    for (int s0 = 0; s0 < NSEG; s0 += blockDim.x) {
        int seg = s0 + t;
        int cnt = (seg < NSEG) ? g_segcnt[b * MAX_SEG + seg] : 0;
        s_dat[t] = cnt;
        __syncthreads();
        // Hillis-Steele inclusive scan over 256
        #pragma unroll
        for (int off = 1; off < 256; off <<= 1) {
            int v = (t >= off) ? s_dat[t - off] : 0;
            __syncthreads();
            s_dat[t] += v;
            __syncthreads();
        }
        int incl  = s_dat[t];
        int total = s_dat[255];
        int epref = base + incl - cnt;

        if (seg < NSEG && cnt > 0 && epref < M) {
            int r = epref;
            int abase = b * A + seg * 256;
            int lim = min(256, A - seg * 256);
            #pragma unroll 8
            for (int j = 0; j < lim; j++) {
                if (r >= M) break;
                uint32_t mm = g_meta[abase + j];
                if (((mm >> 6) & 3u) == 2u) { g_table[b * M + r] = (int)(mm & 63u); r++; }
            }
        }
        base += total;
        __syncthreads();
    }
    if (t == 0) g_numpos[b] = base;
}

// focal element with state mask folded in as arithmetic (no load guard)
__device__ __forceinline__ float focal_elem(float c, bool is_one, bool active) {
    c = fminf(fmaxf(c, 1e-4f), 0.9999f);
    float o = 1.0f - c;
    float w = is_one ? 0.25f * o * o : 0.75f * c * c;
    float l = -__logf(is_one ? c : o);
    return active ? w * l : 0.0f;
}

__device__ __forceinline__ float smooth_l1(float d) {
    return (d <= 1.0f / 9.0f) ? (4.5f * d * d) : (d - 0.5f / 9.0f);
}

// ---------------------------------------------------------------------------
// fused focal + regression. grid = (NBLK, B), 256 threads.
// thread t: anchor = a0 + (t>>4), channels 4*(t&15)..+3 as float4.
// cls float4 loads are UNCONDITIONAL (address depends only on index) so the
// memory pipeline streams at full MLP; meta only gates the arithmetic.
// thread with (t&15)==0 additionally handles the regression loss of its anchor.
// ---------------------------------------------------------------------------
__global__ void fused_kernel(const float* __restrict__ cls,
                             const float* __restrict__ regs,
                             const float* __restrict__ anchors,
                             const float* __restrict__ ann,
                             int A, int C, int M) {
    int b  = blockIdx.y;
    int t  = threadIdx.x;
    int la = t >> 4;       // 0..15
    int c4 = t & 15;       // 0..15

    float cl_acc = 0.0f, xy_acc = 0.0f, ang_acc = 0.0f;
    const uint16_t* meta_b = g_meta + (size_t)b * A;
    const float*    cls_b  = cls + (size_t)b * A * C;

    for (int a0 = blockIdx.x * 16; a0 < A; a0 += gridDim.x * 16) {
        int a = a0 + la;
        if (a >= A) continue;
        uint32_t m = meta_b[a];
        int state = (int)((m >> 6) & 3u);
        bool active = (state != 0);
        int tgt = (state == 2) ? (int)(m >> 8) : -1;

        for (int col = c4 * 4; col < C; col += 64) {
            const float4 v = *(const float4*)(cls_b + (size_t)a * C + col);
            cl_acc += focal_elem(v.x, col + 0 == tgt, active);
            cl_acc += focal_elem(v.y, col + 1 == tgt, active);
            cl_acc += focal_elem(v.z, col + 2 == tgt, active);
            cl_acc += focal_elem(v.w, col + 3 == tgt, active);
        }

        if (c4 == 0 && state == 2) {
            int gi = g_table[b * M + (m & 63u)];
            const float* g  = ann + (size_t)(b * M + gi) * 4;
            const float* rg = regs + ((size_t)b * A + a) * 3;
            float tx = g[0] - anchors[a * 3 + 0];
            float ty = g[1] - anchors[a * 3 + 1];
            float ta = g[2] - anchors[a * 3 + 2];
            xy_acc  += smooth_l1(fabsf(tx - rg[0])) + smooth_l1(fabsf(ty - rg[1]));
            ang_acc += 1.0f - cosf(ta - rg[2]);
        }
    }

    // block reduce 3 values
    __shared__ float s_c[8], s_x[8], s_a[8];
    #pragma unroll
    for (int o = 16; o > 0; o >>= 1) {
        cl_acc  += __shfl_down_sync(0xffffffffu, cl_acc,  o);
        xy_acc  += __shfl_down_sync(0xffffffffu, xy_acc,  o);
        ang_acc += __shfl_down_sync(0xffffffffu, ang_acc, o);
    }
    int lane = t & 31, wid = t >> 5;
    if (lane == 0) { s_c[wid] = cl_acc; s_x[wid] = xy_acc; s_a[wid] = ang_acc; }
    __syncthreads();
    if (wid == 0) {
        float vc = (lane < 8) ? s_c[lane] : 0.0f;
        float vx = (lane < 8) ? s_x[lane] : 0.0f;
        float va = (lane < 8) ? s_a[lane] : 0.0f;
        #pragma unroll
        for (int o = 4; o > 0; o >>= 1) {
            vc += __shfl_down_sync(0xffffffffu, vc, o);
            vx += __shfl_down_sync(0xffffffffu, vx, o);
            va += __shfl_down_sync(0xffffffffu, va, o);
        }
        if (lane == 0) {
            int slot = blockIdx.x & (NSLOT - 1);
            atomicAdd(&g_cls_part[b * NSLOT + slot], (double)vc);
            if (vx != 0.0f) atomicAdd(&g_xy_part [b * NSLOT + slot], (double)vx);
            if (va != 0.0f) atomicAdd(&g_ang_part[b * NSLOT + slot], (double)va);
        }
    }
}

// ---------------------------------------------------------------------------
// finalize: one warp per image, lane = partial slot; warp-reduce doubles.
// ---------------------------------------------------------------------------
__global__ void finalize_kernel(float* __restrict__ out, int B) {
    int wid  = threadIdx.x >> 5;
    int lane = threadIdx.x & 31;
    __shared__ double s_cl[8], s_xy[8], s_ang[8];

    if (wid < B) {
        double sc = g_cls_part[wid * NSLOT + lane];
        double sx = g_xy_part [wid * NSLOT + lane];
        double sa = g_ang_part[wid * NSLOT + lane];
        #pragma unroll
        for (int o = 16; o > 0; o >>= 1) {
            sc += __shfl_down_sync(0xffffffffu, sc, o);
            sx += __shfl_down_sync(0xffffffffu, sx, o);
            sa += __shfl_down_sync(0xffffffffu, sa, o);
        }
        if (lane == 0) {
            double np = (double)max(g_numpos[wid], 1);
            s_cl[wid]  = sc / np;
            s_xy[wid]  = sx / (2.0 * np);
            s_ang[wid] = sa / np;
        }
    }
    __syncthreads();
    if (threadIdx.x == 0) {
        double cl = 0.0, xy = 0.0, ag = 0.0;
        for (int b = 0; b < B; b++) { cl += s_cl[b]; xy += s_xy[b]; ag += s_ang[b]; }
        out[0] = (float)(cl / B);
        out[1] = (float)(xy / B);
        out[2] = (float)(ag / B);
    }
}

extern "C" void kernel_launch(void* const* d_in, const int* in_sizes, int n_in,
                              void* d_out, int out_size) {
    const float* cls     = (const float*)d_in[0];
    const float* regs    = (const float*)d_in[1];
    const float* anchors = (const float*)d_in[2];
    const float* ann     = (const float*)d_in[3];
    float* out = (float*)d_out;

    int A = in_sizes[2] / 3;                 // anchors [1, A, 3]
    int B = in_sizes[1] / (3 * A);           // regressions [B, A, 3]
    int C = in_sizes[0] / (B * A);           // classifications [B, A, C]
    int M = in_sizes[3] / (4 * B);           // annotations [B, M, 4]
    int NSEG = (A + 255) / 256;

    dim3 ag(NSEG, B);
    assign_kernel<<<ag, 256>>>(anchors, ann, A, M);

    scan_kernel<<<B, 256>>>(A, M, NSEG);

    dim3 fg(512, B);
    fused_kernel<<<fg, 256>>>(cls, regs, anchors, ann, A, C, M);

    finalize_kernel<<<1, 32 * ((B + 0) > 8 ? 8 : (B < 1 ? 1 : B))>>>(out, B);
}